// round 10
// baseline (speedup 1.0000x reference)
#include <cuda_runtime.h>
#include <cuda_bf16.h>
#include <cuda_fp16.h>
#include <cstdint>
#include <math.h>

#define B 64
#define S 2048
#define H 512
#define E 1024   // 2*H
#define NCHUNK 32

// ---------------------------------------------------------------------------
// Device scratch (allocation-free rule)
// ---------------------------------------------------------------------------
__device__ float g_proj_dec[B * H];
__device__ float g_scores_part[2][B * S];
__device__ float g_ctx_part[NCHUNK][B * E];
__device__ __half g_Wh16[E * H];   // [k][n] fp16(W_h)

// ---------------------------------------------------------------------------
// Helpers
// ---------------------------------------------------------------------------
__device__ __forceinline__ uint32_t smem_u32(const void* p) {
    uint32_t a;
    asm("{ .reg .u64 t; cvta.to.shared.u64 t, %1; cvt.u32.u64 %0, t; }" : "=r"(a) : "l"(p));
    return a;
}
__device__ __forceinline__ void cp16(uint32_t dst, const void* src) {
    asm volatile("cp.async.cg.shared.global [%0], [%1], 16;" :: "r"(dst), "l"(src));
}
__device__ __forceinline__ void cp_commit() {
    asm volatile("cp.async.commit_group;" ::: "memory");
}
__device__ __forceinline__ void cp_wait1() {
    asm volatile("cp.async.wait_group 1;" ::: "memory");
}
__device__ __forceinline__ void ldsm_x4(uint32_t addr, uint32_t* r) {
    asm volatile("ldmatrix.sync.aligned.m8n8.x4.shared.b16 {%0,%1,%2,%3}, [%4];"
                 : "=r"(r[0]), "=r"(r[1]), "=r"(r[2]), "=r"(r[3]) : "r"(addr));
}
__device__ __forceinline__ void ldsm_x4_t(uint32_t addr, uint32_t* r) {
    asm volatile("ldmatrix.sync.aligned.m8n8.x4.trans.shared.b16 {%0,%1,%2,%3}, [%4];"
                 : "=r"(r[0]), "=r"(r[1]), "=r"(r[2]), "=r"(r[3]) : "r"(addr));
}
__device__ __forceinline__ void mma_fp16(float* c, const uint32_t* a, uint32_t b0, uint32_t b1) {
    asm volatile("mma.sync.aligned.m16n8k16.row.col.f32.f16.f16.f32 "
                 "{%0,%1,%2,%3}, {%4,%5,%6,%7}, {%8,%9}, {%0,%1,%2,%3};"
                 : "+f"(c[0]), "+f"(c[1]), "+f"(c[2]), "+f"(c[3])
                 : "r"(a[0]), "r"(a[1]), "r"(a[2]), "r"(a[3]), "r"(b0), "r"(b1));
}
__device__ __forceinline__ uint32_t pack_h2(float x, float y) {
    __half2 h = __floats2half2_rn(x, y);
    return *reinterpret_cast<uint32_t*>(&h);
}
// hardware tanh (MUFU.TANH, sm_75+): |err| ~ 2^-11, far below fp16 GEMM noise
__device__ __forceinline__ float tanh_hw(float x) {
    float y;
    asm("tanh.approx.f32 %0, %1;" : "=f"(y) : "f"(x));
    return y;
}

// ---------------------------------------------------------------------------
// Kernel 0+1 merged: blocks [0,2048) convert W_h -> fp16;
//                    blocks [2048,2112) compute proj_dec row b = blk-2048.
// ---------------------------------------------------------------------------
__global__ __launch_bounds__(256) void prep_kernel(
    const float* __restrict__ Wh,
    const float* __restrict__ dec, const float* __restrict__ Wd)
{
    const int blk = blockIdx.x;
    const int tid = threadIdx.x;
    if (blk < (E * H) / 256) {
        int i = blk * 256 + tid;
        g_Wh16[i] = __float2half_rn(Wh[i]);
    } else {
        __shared__ float dsh[H];
        const int b = blk - (E * H) / 256;
        dsh[tid]       = dec[b * H + tid];
        dsh[tid + 256] = dec[b * H + tid + 256];
        __syncthreads();
        float s0 = 0.f, s1 = 0.f;
#pragma unroll 8
        for (int d = 0; d < H; ++d) {
            float dv = dsh[d];
            s0 += dv * Wd[d * H + tid];
            s1 += dv * Wd[d * H + tid + 256];
        }
        g_proj_dec[b * H + tid]       = s0;
        g_proj_dec[b * H + tid + 256] = s1;
    }
}

// ---------------------------------------------------------------------------
// Kernel 2: scores via single-term fp16 mma.sync + fused tanh·v epilogue
// Block tile: 128(M) x 256(N), BK=32, 16 warps (2x8), warp tile 64x32.
// Depth-2 A register prefetch; cvt runs in the MMA shadow.
// Grid: (2, 1024). blockIdx.x = n-pass (0/1), blockIdx.y = row block.
// ---------------------------------------------------------------------------
#define KSTEPS 32   // 1024 / 32

// Dynamic SMEM layout (bytes)
#define SW_BUF   0         // 3 x 16384
#define SA_BUF   49152     // 2 x 8192
#define S_PD     65536     // 256 f32
#define S_V      66560     // 256 f32
#define S_RED    67584     // 128*8 f32 = 4KB
#define SM_TOT   71680

__global__ void __launch_bounds__(512, 1) scores_mma_kernel(
    const float* __restrict__ enc, const float* __restrict__ v)
{
    extern __shared__ char smem[];
    const uint32_t sb = smem_u32(smem);
    const int tid  = threadIdx.x;
    const int lane = tid & 31;
    const int warp = tid >> 5;
    const int wm   = warp >> 3;        // 0..1
    const int wn   = warp & 7;         // 0..7
    const int ny   = blockIdx.x;       // 0..1 (n-pass)
    const int row0 = blockIdx.y * 128;
    const int b    = row0 >> 11;       // S = 2048

    float* pd_sh = (float*)(smem + S_PD);
    float* v_sh  = (float*)(smem + S_V);
    float* red   = (float*)(smem + S_RED);
    if (tid < 256) {
        pd_sh[tid] = g_proj_dec[b * H + ny * 256 + tid];
        v_sh[tid]  = v[ny * 256 + tid];
    }

    // A (enc) load mapping: 4 threads per row, 8 k-elems (32B) each
    const int am = tid >> 2;           // 0..127
    const int ap = tid & 3;            // 16B group within 64B row
    const float* aptr = enc + (size_t)(row0 + am) * E + ap * 8;

    const __half* wbase = g_Wh16 + ny * 256;

    float c[4][4][4];
#pragma unroll
    for (int mt = 0; mt < 4; mt++)
#pragma unroll
        for (int j = 0; j < 4; j++)
#pragma unroll
            for (int q = 0; q < 4; q++) c[mt][j][q] = 0.f;

    uint4 pref[2][2];   // depth-2 prefetch: pref[st & 1]

    // ---- lambdas ----
    auto issueW = [&](int st) {
        uint32_t wb = sb + SW_BUF + (uint32_t)(st % 3) * 16384u;
        const __half* bh = wbase + (size_t)(st * 32) * H;
#pragma unroll
        for (int it = 0; it < 2; it++) {
            int idx = tid + it * 512;
            int k = idx >> 5;          // 0..31
            int g = idx & 31;          // 16B group (8 fp16)
            uint32_t off = (uint32_t)(k * 512 + ((g ^ (k & 7)) << 4));
            cp16(wb + off, bh + (size_t)k * H + g * 8);
        }
    };
    auto ldA = [&](int st) {
        const float4* p = (const float4*)(aptr + st * 32);
        pref[st & 1][0] = *(const uint4*)(p);
        pref[st & 1][1] = *(const uint4*)(p + 1);
    };
    auto cvtStsA = [&](int st) {
        char* ab = smem + SA_BUF + (st & 1) * 8192;
        float4 f0 = *(float4*)&pref[st & 1][0];
        float4 f1 = *(float4*)&pref[st & 1][1];
        uint4 hv;
        hv.x = pack_h2(f0.x, f0.y);
        hv.y = pack_h2(f0.z, f0.w);
        hv.z = pack_h2(f1.x, f1.y);
        hv.w = pack_h2(f1.z, f1.w);
        uint32_t off = (uint32_t)(am * 64 + ((ap ^ ((am >> 1) & 3)) << 4));
        *(uint4*)(ab + off) = hv;
    };
    auto doMMA = [&](int st) {
        uint32_t ab = sb + SA_BUF + (uint32_t)(st & 1) * 8192u;
        uint32_t wb = sb + SW_BUF + (uint32_t)(st % 3) * 16384u;
#pragma unroll
        for (int ks = 0; ks < 2; ks++) {
            uint32_t ah[4][4], bh[2][4];
            const int mrb = wm * 64 + (lane & 15);
            const int kg  = ks * 2 + (lane >> 4);
#pragma unroll
            for (int mt = 0; mt < 4; mt++) {
                int m = mrb + mt * 16;
                uint32_t off = (uint32_t)(m * 64 + ((kg ^ ((m >> 1) & 3)) << 4));
                ldsm_x4(ab + off, ah[mt]);
            }
            const int kr = ks * 16 + (lane & 7) + ((lane >> 3) & 1) * 8;
#pragma unroll
            for (int jj = 0; jj < 2; jj++) {
                int ng = wn * 4 + jj * 2 + (lane >> 4);
                uint32_t off = (uint32_t)(kr * 512 + ((ng ^ (kr & 7)) << 4));
                ldsm_x4_t(wb + off, bh[jj]);
            }
#pragma unroll
            for (int mt = 0; mt < 4; mt++)
#pragma unroll
                for (int j = 0; j < 4; j++) {
                    uint32_t b0 = bh[j >> 1][(j & 1) * 2];
                    uint32_t b1 = bh[j >> 1][(j & 1) * 2 + 1];
                    mma_fp16(c[mt][j], ah[mt], b0, b1);
                }
        }
    };

    // ---- prologue ----
    issueW(0); cp_commit();
    issueW(1); cp_commit();
    ldA(0);
    ldA(1);
    cvtStsA(0);
    cp_wait1();
    __syncthreads();

    // ---- main loop ----
    for (int i = 0; i < KSTEPS; i++) {
        const bool more = (i + 1 < KSTEPS);
        if (i + 2 < KSTEPS) {
            ldA(i + 2);
            issueW(i + 2);
        }
        cp_commit();                       // one group per iter (may be empty)
        if (more) cvtStsA(i + 1);          // data already resident (depth-2)
        doMMA(i);
        if (more) {
            cp_wait1();
            __syncthreads();
        }
    }

    // ---- epilogue: partial scores over this 256-n slice ----
    float p[4][2];
#pragma unroll
    for (int mt = 0; mt < 4; mt++) { p[mt][0] = 0.f; p[mt][1] = 0.f; }
#pragma unroll
    for (int mt = 0; mt < 4; mt++)
#pragma unroll
        for (int j = 0; j < 4; j++) {
            int nn = wn * 32 + j * 8 + ((lane & 3) << 1);
            float pd0 = pd_sh[nn], pd1 = pd_sh[nn + 1];
            float v0 = v_sh[nn], v1 = v_sh[nn + 1];
            p[mt][0] += tanh_hw(c[mt][j][0] + pd0) * v0 + tanh_hw(c[mt][j][1] + pd1) * v1;
            p[mt][1] += tanh_hw(c[mt][j][2] + pd0) * v0 + tanh_hw(c[mt][j][3] + pd1) * v1;
        }
#pragma unroll
    for (int mt = 0; mt < 4; mt++) {
        float p0 = p[mt][0], p1 = p[mt][1];
        p0 += __shfl_xor_sync(0xFFFFFFFF, p0, 1);
        p0 += __shfl_xor_sync(0xFFFFFFFF, p0, 2);
        p1 += __shfl_xor_sync(0xFFFFFFFF, p1, 1);
        p1 += __shfl_xor_sync(0xFFFFFFFF, p1, 2);
        if ((lane & 3) == 0) {
            int r = wm * 64 + mt * 16 + (lane >> 2);
            red[r * 8 + wn]       = p0;
            red[(r + 8) * 8 + wn] = p1;
        }
    }
    __syncthreads();
    if (tid < 128) {
        float s = 0.f;
#pragma unroll
        for (int t = 0; t < 8; t++) s += red[tid * 8 + t];
        g_scores_part[ny][row0 + tid] = s;
    }
}

// ---------------------------------------------------------------------------
// Kernel 3: mask + softmax (sums the two n-pass partials), 512 threads
// ---------------------------------------------------------------------------
__global__ __launch_bounds__(512) void softmax_kernel(
    const int* __restrict__ mask, float* __restrict__ attn)
{
    __shared__ float buf[S];
    __shared__ float redv[512];
    const int b = blockIdx.x;
    const int tid = threadIdx.x;

    float mx = -INFINITY;
#pragma unroll
    for (int s = tid; s < S; s += 512) {
        float sc = (mask[b * S + s] == 0)
                 ? -10000.0f
                 : (g_scores_part[0][b * S + s] + g_scores_part[1][b * S + s]);
        buf[s] = sc;
        mx = fmaxf(mx, sc);
    }
    redv[tid] = mx;
    __syncthreads();
    for (int st = 256; st > 0; st >>= 1) {
        if (tid < st) redv[tid] = fmaxf(redv[tid], redv[tid + st]);
        __syncthreads();
    }
    mx = redv[0];
    __syncthreads();

    float sum = 0.f;
#pragma unroll
    for (int s = tid; s < S; s += 512) {
        float e = __expf(buf[s] - mx);
        buf[s] = e;
        sum += e;
    }
    redv[tid] = sum;
    __syncthreads();
    for (int st = 256; st > 0; st >>= 1) {
        if (tid < st) redv[tid] += redv[tid + st];
        __syncthreads();
    }
    float inv = 1.0f / redv[0];
#pragma unroll
    for (int s = tid; s < S; s += 512)
        attn[b * S + s] = buf[s] * inv;
}

// ---------------------------------------------------------------------------
// Kernel 4: context partials. grid (B, NCHUNK). Dual accumulators for ILP.
// ---------------------------------------------------------------------------
__global__ __launch_bounds__(256) void context_part_kernel(
    const float* __restrict__ enc, const float* __restrict__ attn)
{
    __shared__ float w[S / NCHUNK];
    const int b = blockIdx.x;
    const int chunk = blockIdx.y;
    const int tid = threadIdx.x;
    const int s0 = chunk * (S / NCHUNK);

    for (int s = tid; s < S / NCHUNK; s += 256)
        w[s] = attn[b * S + s0 + s];
    __syncthreads();

    const float4* e4 = (const float4*)(enc + ((size_t)b * S + s0) * E);
    float4 c0 = make_float4(0.f, 0.f, 0.f, 0.f);
    float4 c1 = make_float4(0.f, 0.f, 0.f, 0.f);
#pragma unroll 4
    for (int s = 0; s < S / NCHUNK; s += 2) {
        float4 ea = e4[(size_t)s * (E / 4) + tid];
        float4 eb = e4[(size_t)(s + 1) * (E / 4) + tid];
        float wa = w[s], wb = w[s + 1];
        c0.x += wa * ea.x; c0.y += wa * ea.y;
        c0.z += wa * ea.z; c0.w += wa * ea.w;
        c1.x += wb * eb.x; c1.y += wb * eb.y;
        c1.z += wb * eb.z; c1.w += wb * eb.w;
    }
    c0.x += c1.x; c0.y += c1.y; c0.z += c1.z; c0.w += c1.w;
    ((float4*)(&g_ctx_part[chunk][b * E]))[tid] = c0;
}

// ---------------------------------------------------------------------------
// Kernel 5: reduce context partials into d_out.
// ---------------------------------------------------------------------------
__global__ __launch_bounds__(256) void context_reduce_kernel(float* __restrict__ ctx)
{
    const int b = blockIdx.x;
    const int tid = threadIdx.x;
    float4 c = make_float4(0.f, 0.f, 0.f, 0.f);
#pragma unroll
    for (int ch = 0; ch < NCHUNK; ++ch) {
        float4 p = ((const float4*)(&g_ctx_part[ch][b * E]))[tid];
        c.x += p.x; c.y += p.y; c.z += p.z; c.w += p.w;
    }
    ((float4*)(ctx + b * E))[tid] = c;
}

// ---------------------------------------------------------------------------
extern "C" void kernel_launch(void* const* d_in, const int* in_sizes, int n_in,
                              void* d_out, int out_size)
{
    const float* dec  = (const float*)d_in[0];  // (B, H)
    const float* enc  = (const float*)d_in[1];  // (B, S, 2H)
    const int*   mask = (const int*)  d_in[2];  // (B, S)
    const float* Wh   = (const float*)d_in[3];  // (2H, H)
    const float* Wd   = (const float*)d_in[4];  // (H, H)
    const float* v    = (const float*)d_in[5];  // (H,)

    float* out  = (float*)d_out;
    float* ctx  = out;             // (B, 2H)
    float* attn = out + B * E;     // (B, S)

    cudaFuncSetAttribute(scores_mma_kernel,
                         cudaFuncAttributeMaxDynamicSharedMemorySize, SM_TOT);

    prep_kernel<<<(E * H) / 256 + B, 256>>>(Wh, dec, Wd);
    dim3 gs(2, (B * S) / 128);
    scores_mma_kernel<<<gs, 512, SM_TOT>>>(enc, v);
    softmax_kernel<<<B, 512>>>(mask, attn);
    dim3 gctx(B, NCHUNK);
    context_part_kernel<<<gctx, 256>>>(enc, attn);
    context_reduce_kernel<<<B, 256>>>(ctx);
}

// round 11
// speedup vs baseline: 1.5645x; 1.5645x over previous
#include <cuda_runtime.h>
#include <cuda_bf16.h>
#include <cuda_fp16.h>
#include <cstdint>
#include <math.h>

#define B 64
#define S 2048
#define H 512
#define E 1024   // 2*H
#define NCHUNK 16

// ---------------------------------------------------------------------------
// Device scratch (allocation-free rule)
// ---------------------------------------------------------------------------
__device__ float g_proj_dec[B * H];
__device__ float g_scores_part[2][B * S];
__device__ float g_ctx_part[NCHUNK][B * E];
__device__ __half g_Wh16[E * H];   // [k][n] fp16(W_h)

// ---------------------------------------------------------------------------
// Helpers
// ---------------------------------------------------------------------------
__device__ __forceinline__ uint32_t smem_u32(const void* p) {
    uint32_t a;
    asm("{ .reg .u64 t; cvta.to.shared.u64 t, %1; cvt.u32.u64 %0, t; }" : "=r"(a) : "l"(p));
    return a;
}
__device__ __forceinline__ void cp16(uint32_t dst, const void* src) {
    asm volatile("cp.async.cg.shared.global [%0], [%1], 16;" :: "r"(dst), "l"(src));
}
__device__ __forceinline__ void cp_commit() {
    asm volatile("cp.async.commit_group;" ::: "memory");
}
__device__ __forceinline__ void cp_wait1() {
    asm volatile("cp.async.wait_group 1;" ::: "memory");
}
__device__ __forceinline__ void ldsm_x4(uint32_t addr, uint32_t* r) {
    asm volatile("ldmatrix.sync.aligned.m8n8.x4.shared.b16 {%0,%1,%2,%3}, [%4];"
                 : "=r"(r[0]), "=r"(r[1]), "=r"(r[2]), "=r"(r[3]) : "r"(addr));
}
__device__ __forceinline__ void ldsm_x4_t(uint32_t addr, uint32_t* r) {
    asm volatile("ldmatrix.sync.aligned.m8n8.x4.trans.shared.b16 {%0,%1,%2,%3}, [%4];"
                 : "=r"(r[0]), "=r"(r[1]), "=r"(r[2]), "=r"(r[3]) : "r"(addr));
}
__device__ __forceinline__ void mma_fp16(float* c, const uint32_t* a, uint32_t b0, uint32_t b1) {
    asm volatile("mma.sync.aligned.m16n8k16.row.col.f32.f16.f16.f32 "
                 "{%0,%1,%2,%3}, {%4,%5,%6,%7}, {%8,%9}, {%0,%1,%2,%3};"
                 : "+f"(c[0]), "+f"(c[1]), "+f"(c[2]), "+f"(c[3])
                 : "r"(a[0]), "r"(a[1]), "r"(a[2]), "r"(a[3]), "r"(b0), "r"(b1));
}
__device__ __forceinline__ uint32_t pack_h2(float x, float y) {
    __half2 h = __floats2half2_rn(x, y);
    return *reinterpret_cast<uint32_t*>(&h);
}
// hardware tanh (MUFU.TANH, sm_75+): |err| ~ 2^-11, far below fp16 GEMM noise
__device__ __forceinline__ float tanh_hw(float x) {
    float y;
    asm("tanh.approx.f32 %0, %1;" : "=f"(y) : "f"(x));
    return y;
}

// ---------------------------------------------------------------------------
// Kernel 0+1 merged: blocks [0,2048) convert W_h -> fp16;
//                    blocks [2048,2112) compute proj_dec row b = blk-2048.
// ---------------------------------------------------------------------------
__global__ __launch_bounds__(256) void prep_kernel(
    const float* __restrict__ Wh,
    const float* __restrict__ dec, const float* __restrict__ Wd)
{
    const int blk = blockIdx.x;
    const int tid = threadIdx.x;
    if (blk < (E * H) / 256) {
        int i = blk * 256 + tid;
        g_Wh16[i] = __float2half_rn(Wh[i]);
    } else {
        __shared__ float dsh[H];
        const int b = blk - (E * H) / 256;
        dsh[tid]       = dec[b * H + tid];
        dsh[tid + 256] = dec[b * H + tid + 256];
        __syncthreads();
        float s0 = 0.f, s1 = 0.f;
#pragma unroll 8
        for (int d = 0; d < H; ++d) {
            float dv = dsh[d];
            s0 += dv * Wd[d * H + tid];
            s1 += dv * Wd[d * H + tid + 256];
        }
        g_proj_dec[b * H + tid]       = s0;
        g_proj_dec[b * H + tid + 256] = s1;
    }
}

// ---------------------------------------------------------------------------
// Kernel 2: scores via single-term fp16 mma.sync + fused tanh·v epilogue
// Block tile: 128(M) x 256(N), BK=32, 16 warps (2x8), warp tile 64x32.
// Grid: (2, 1024). blockIdx.x = n-pass (0/1), blockIdx.y = row block.
// (R9 structure — do not reorder: the flat pref[2] + doMMA-then-cvt order
//  is a measured local optimum; deviations cost 50-300us.)
// ---------------------------------------------------------------------------
#define KSTEPS 32   // 1024 / 32

// Dynamic SMEM layout (bytes)
#define SW_BUF   0         // 3 x 16384
#define SA_BUF   49152     // 2 x 8192
#define S_PD     65536     // 256 f32
#define S_V      66560     // 256 f32
#define S_RED    67584     // 128*8 f32 = 4KB
#define SM_TOT   71680

__global__ void __launch_bounds__(512, 1) scores_mma_kernel(
    const float* __restrict__ enc, const float* __restrict__ v)
{
    extern __shared__ char smem[];
    const uint32_t sb = smem_u32(smem);
    const int tid  = threadIdx.x;
    const int lane = tid & 31;
    const int warp = tid >> 5;
    const int wm   = warp >> 3;        // 0..1
    const int wn   = warp & 7;         // 0..7
    const int ny   = blockIdx.x;       // 0..1 (n-pass)
    const int row0 = blockIdx.y * 128;
    const int b    = row0 >> 11;       // S = 2048

    float* pd_sh = (float*)(smem + S_PD);
    float* v_sh  = (float*)(smem + S_V);
    float* red   = (float*)(smem + S_RED);
    if (tid < 256) {
        pd_sh[tid] = g_proj_dec[b * H + ny * 256 + tid];
        v_sh[tid]  = v[ny * 256 + tid];
    }

    // A (enc) load mapping: 4 threads per row, 8 k-elems (32B) each
    const int am = tid >> 2;           // 0..127
    const int ap = tid & 3;            // 16B group within 64B row
    const float* aptr = enc + (size_t)(row0 + am) * E + ap * 8;

    const __half* wbase = g_Wh16 + ny * 256;

    float c[4][4][4];
#pragma unroll
    for (int mt = 0; mt < 4; mt++)
#pragma unroll
        for (int j = 0; j < 4; j++)
#pragma unroll
            for (int q = 0; q < 4; q++) c[mt][j][q] = 0.f;

    uint4 pref[2];

    // ---- lambdas ----
    auto issueW = [&](int st) {
        uint32_t wb = sb + SW_BUF + (uint32_t)(st % 3) * 16384u;
        const __half* bh = wbase + (size_t)(st * 32) * H;
#pragma unroll
        for (int it = 0; it < 2; it++) {
            int idx = tid + it * 512;
            int k = idx >> 5;          // 0..31
            int g = idx & 31;          // 16B group (8 fp16)
            uint32_t off = (uint32_t)(k * 512 + ((g ^ (k & 7)) << 4));
            cp16(wb + off, bh + (size_t)k * H + g * 8);
        }
    };
    auto ldA = [&](int st) {
        const float4* p = (const float4*)(aptr + st * 32);
        pref[0] = *(const uint4*)(p);
        pref[1] = *(const uint4*)(p + 1);
    };
    auto cvtStsA = [&](int st) {
        char* ab = smem + SA_BUF + (st & 1) * 8192;
        float4 f0 = *(float4*)&pref[0];
        float4 f1 = *(float4*)&pref[1];
        uint4 hv;
        hv.x = pack_h2(f0.x, f0.y);
        hv.y = pack_h2(f0.z, f0.w);
        hv.z = pack_h2(f1.x, f1.y);
        hv.w = pack_h2(f1.z, f1.w);
        uint32_t off = (uint32_t)(am * 64 + ((ap ^ ((am >> 1) & 3)) << 4));
        *(uint4*)(ab + off) = hv;
    };
    auto doMMA = [&](int st) {
        uint32_t ab = sb + SA_BUF + (uint32_t)(st & 1) * 8192u;
        uint32_t wb = sb + SW_BUF + (uint32_t)(st % 3) * 16384u;
#pragma unroll
        for (int ks = 0; ks < 2; ks++) {
            uint32_t ah[4][4], bh[2][4];
            const int mrb = wm * 64 + (lane & 15);
            const int kg  = ks * 2 + (lane >> 4);
#pragma unroll
            for (int mt = 0; mt < 4; mt++) {
                int m = mrb + mt * 16;
                uint32_t off = (uint32_t)(m * 64 + ((kg ^ ((m >> 1) & 3)) << 4));
                ldsm_x4(ab + off, ah[mt]);
            }
            const int kr = ks * 16 + (lane & 7) + ((lane >> 3) & 1) * 8;
#pragma unroll
            for (int jj = 0; jj < 2; jj++) {
                int ng = wn * 4 + jj * 2 + (lane >> 4);
                uint32_t off = (uint32_t)(kr * 512 + ((ng ^ (kr & 7)) << 4));
                ldsm_x4_t(wb + off, bh[jj]);
            }
#pragma unroll
            for (int mt = 0; mt < 4; mt++)
#pragma unroll
                for (int j = 0; j < 4; j++) {
                    uint32_t b0 = bh[j >> 1][(j & 1) * 2];
                    uint32_t b1 = bh[j >> 1][(j & 1) * 2 + 1];
                    mma_fp16(c[mt][j], ah[mt], b0, b1);
                }
        }
    };

    // ---- prologue ----
    issueW(0); cp_commit();
    issueW(1); cp_commit();
    ldA(0);
    cvtStsA(0);
    cp_wait1();
    __syncthreads();

    // ---- main loop ----
    for (int i = 0; i < KSTEPS; i++) {
        const bool more = (i + 1 < KSTEPS);
        if (more) ldA(i + 1);
        if (i + 2 < KSTEPS) issueW(i + 2);
        cp_commit();                       // one group per iter (may be empty)
        doMMA(i);
        if (more) {
            cvtStsA(i + 1);
            cp_wait1();
            __syncthreads();
        }
    }

    // ---- epilogue: partial scores over this 256-n slice ----
    float p[4][2];
#pragma unroll
    for (int mt = 0; mt < 4; mt++) { p[mt][0] = 0.f; p[mt][1] = 0.f; }
#pragma unroll
    for (int mt = 0; mt < 4; mt++)
#pragma unroll
        for (int j = 0; j < 4; j++) {
            int nn = wn * 32 + j * 8 + ((lane & 3) << 1);
            float pd0 = pd_sh[nn], pd1 = pd_sh[nn + 1];
            float v0 = v_sh[nn], v1 = v_sh[nn + 1];
            p[mt][0] += tanh_hw(c[mt][j][0] + pd0) * v0 + tanh_hw(c[mt][j][1] + pd1) * v1;
            p[mt][1] += tanh_hw(c[mt][j][2] + pd0) * v0 + tanh_hw(c[mt][j][3] + pd1) * v1;
        }
#pragma unroll
    for (int mt = 0; mt < 4; mt++) {
        float p0 = p[mt][0], p1 = p[mt][1];
        p0 += __shfl_xor_sync(0xFFFFFFFF, p0, 1);
        p0 += __shfl_xor_sync(0xFFFFFFFF, p0, 2);
        p1 += __shfl_xor_sync(0xFFFFFFFF, p1, 1);
        p1 += __shfl_xor_sync(0xFFFFFFFF, p1, 2);
        if ((lane & 3) == 0) {
            int r = wm * 64 + mt * 16 + (lane >> 2);
            red[r * 8 + wn]       = p0;
            red[(r + 8) * 8 + wn] = p1;
        }
    }
    __syncthreads();
    if (tid < 128) {
        float s = 0.f;
#pragma unroll
        for (int t = 0; t < 8; t++) s += red[tid * 8 + t];
        g_scores_part[ny][row0 + tid] = s;
    }
}

// ---------------------------------------------------------------------------
// Kernel 3: mask + softmax. No max pass: scores bounded (|s| <= sum|v| ~ 20),
// masked -10000 -> expf underflows to exactly 0 (matches reference where()).
// ---------------------------------------------------------------------------
__global__ __launch_bounds__(512) void softmax_kernel(
    const int* __restrict__ mask, float* __restrict__ attn)
{
    __shared__ float buf[S];
    __shared__ float redv[512];
    const int b = blockIdx.x;
    const int tid = threadIdx.x;

    float sum = 0.f;
#pragma unroll
    for (int s = tid; s < S; s += 512) {
        float e = (mask[b * S + s] == 0)
                ? 0.0f
                : __expf(g_scores_part[0][b * S + s] + g_scores_part[1][b * S + s]);
        buf[s] = e;
        sum += e;
    }
    redv[tid] = sum;
    __syncthreads();
    for (int st = 256; st > 0; st >>= 1) {
        if (tid < st) redv[tid] += redv[tid + st];
        __syncthreads();
    }
    float inv = 1.0f / redv[0];
#pragma unroll
    for (int s = tid; s < S; s += 512)
        attn[b * S + s] = buf[s] * inv;
}

// ---------------------------------------------------------------------------
// Kernel 4: context partials. grid (B, NCHUNK). Dual accumulators for ILP.
// ---------------------------------------------------------------------------
__global__ __launch_bounds__(256) void context_part_kernel(
    const float* __restrict__ enc, const float* __restrict__ attn)
{
    __shared__ float w[S / NCHUNK];
    const int b = blockIdx.x;
    const int chunk = blockIdx.y;
    const int tid = threadIdx.x;
    const int s0 = chunk * (S / NCHUNK);

    for (int s = tid; s < S / NCHUNK; s += 256)
        w[s] = attn[b * S + s0 + s];
    __syncthreads();

    const float4* e4 = (const float4*)(enc + ((size_t)b * S + s0) * E);
    float4 c0 = make_float4(0.f, 0.f, 0.f, 0.f);
    float4 c1 = make_float4(0.f, 0.f, 0.f, 0.f);
#pragma unroll 4
    for (int s = 0; s < S / NCHUNK; s += 2) {
        float4 ea = e4[(size_t)s * (E / 4) + tid];
        float4 eb = e4[(size_t)(s + 1) * (E / 4) + tid];
        float wa = w[s], wb = w[s + 1];
        c0.x += wa * ea.x; c0.y += wa * ea.y;
        c0.z += wa * ea.z; c0.w += wa * ea.w;
        c1.x += wb * eb.x; c1.y += wb * eb.y;
        c1.z += wb * eb.z; c1.w += wb * eb.w;
    }
    c0.x += c1.x; c0.y += c1.y; c0.z += c1.z; c0.w += c1.w;
    ((float4*)(&g_ctx_part[chunk][b * E]))[tid] = c0;
}

// ---------------------------------------------------------------------------
// Kernel 5: reduce context partials into d_out.
// ---------------------------------------------------------------------------
__global__ __launch_bounds__(256) void context_reduce_kernel(float* __restrict__ ctx)
{
    const int b = blockIdx.x;
    const int tid = threadIdx.x;
    float4 c = make_float4(0.f, 0.f, 0.f, 0.f);
#pragma unroll
    for (int ch = 0; ch < NCHUNK; ++ch) {
        float4 p = ((const float4*)(&g_ctx_part[ch][b * E]))[tid];
        c.x += p.x; c.y += p.y; c.z += p.z; c.w += p.w;
    }
    ((float4*)(ctx + b * E))[tid] = c;
}

// ---------------------------------------------------------------------------
extern "C" void kernel_launch(void* const* d_in, const int* in_sizes, int n_in,
                              void* d_out, int out_size)
{
    const float* dec  = (const float*)d_in[0];  // (B, H)
    const float* enc  = (const float*)d_in[1];  // (B, S, 2H)
    const int*   mask = (const int*)  d_in[2];  // (B, S)
    const float* Wh   = (const float*)d_in[3];  // (2H, H)
    const float* Wd   = (const float*)d_in[4];  // (H, H)
    const float* v    = (const float*)d_in[5];  // (H,)

    float* out  = (float*)d_out;
    float* ctx  = out;             // (B, 2H)
    float* attn = out + B * E;     // (B, S)

    cudaFuncSetAttribute(scores_mma_kernel,
                         cudaFuncAttributeMaxDynamicSharedMemorySize, SM_TOT);

    prep_kernel<<<(E * H) / 256 + B, 256>>>(Wh, dec, Wd);
    dim3 gs(2, (B * S) / 128);
    scores_mma_kernel<<<gs, 512, SM_TOT>>>(enc, v);
    softmax_kernel<<<B, 512>>>(mask, attn);
    dim3 gctx(B, NCHUNK);
    context_part_kernel<<<gctx, 256>>>(enc, attn);
    context_reduce_kernel<<<B, 256>>>(ctx);
}

// round 12
// speedup vs baseline: 1.5754x; 1.0070x over previous
#include <cuda_runtime.h>
#include <cuda_bf16.h>
#include <cuda_fp16.h>
#include <cstdint>
#include <math.h>

#define B 64
#define S 2048
#define H 512
#define E 1024   // 2*H
#define NCHUNK 16

// ---------------------------------------------------------------------------
// Device scratch (allocation-free rule)
// ---------------------------------------------------------------------------
__device__ float g_proj_dec[B * H];
__device__ float g_scores_part[2][B * S];
__device__ float g_ctx_part[NCHUNK][B * E];
__device__ __half g_Wh16[E * H];          // [k][n] fp16(W_h)
__device__ __half g_enc16[134217728];     // fp16 copy of enc, written by scores ny=0

// ---------------------------------------------------------------------------
// Helpers
// ---------------------------------------------------------------------------
__device__ __forceinline__ uint32_t smem_u32(const void* p) {
    uint32_t a;
    asm("{ .reg .u64 t; cvta.to.shared.u64 t, %1; cvt.u32.u64 %0, t; }" : "=r"(a) : "l"(p));
    return a;
}
__device__ __forceinline__ void cp16(uint32_t dst, const void* src) {
    asm volatile("cp.async.cg.shared.global [%0], [%1], 16;" :: "r"(dst), "l"(src));
}
__device__ __forceinline__ void cp_commit() {
    asm volatile("cp.async.commit_group;" ::: "memory");
}
__device__ __forceinline__ void cp_wait1() {
    asm volatile("cp.async.wait_group 1;" ::: "memory");
}
__device__ __forceinline__ void ldsm_x4(uint32_t addr, uint32_t* r) {
    asm volatile("ldmatrix.sync.aligned.m8n8.x4.shared.b16 {%0,%1,%2,%3}, [%4];"
                 : "=r"(r[0]), "=r"(r[1]), "=r"(r[2]), "=r"(r[3]) : "r"(addr));
}
__device__ __forceinline__ void ldsm_x4_t(uint32_t addr, uint32_t* r) {
    asm volatile("ldmatrix.sync.aligned.m8n8.x4.trans.shared.b16 {%0,%1,%2,%3}, [%4];"
                 : "=r"(r[0]), "=r"(r[1]), "=r"(r[2]), "=r"(r[3]) : "r"(addr));
}
__device__ __forceinline__ void mma_fp16(float* c, const uint32_t* a, uint32_t b0, uint32_t b1) {
    asm volatile("mma.sync.aligned.m16n8k16.row.col.f32.f16.f16.f32 "
                 "{%0,%1,%2,%3}, {%4,%5,%6,%7}, {%8,%9}, {%0,%1,%2,%3};"
                 : "+f"(c[0]), "+f"(c[1]), "+f"(c[2]), "+f"(c[3])
                 : "r"(a[0]), "r"(a[1]), "r"(a[2]), "r"(a[3]), "r"(b0), "r"(b1));
}
__device__ __forceinline__ uint32_t pack_h2(float x, float y) {
    __half2 h = __floats2half2_rn(x, y);
    return *reinterpret_cast<uint32_t*>(&h);
}
// hardware tanh (MUFU.TANH, sm_75+): |err| ~ 2^-11, far below fp16 GEMM noise
__device__ __forceinline__ float tanh_hw(float x) {
    float y;
    asm("tanh.approx.f32 %0, %1;" : "=f"(y) : "f"(x));
    return y;
}

// ---------------------------------------------------------------------------
// Kernel 0+1 merged: blocks [0,2048) convert W_h -> fp16;
//                    blocks [2048,2112) compute proj_dec row b = blk-2048.
// ---------------------------------------------------------------------------
__global__ __launch_bounds__(256) void prep_kernel(
    const float* __restrict__ Wh,
    const float* __restrict__ dec, const float* __restrict__ Wd)
{
    const int blk = blockIdx.x;
    const int tid = threadIdx.x;
    if (blk < (E * H) / 256) {
        int i = blk * 256 + tid;
        g_Wh16[i] = __float2half_rn(Wh[i]);
    } else {
        __shared__ float dsh[H];
        const int b = blk - (E * H) / 256;
        dsh[tid]       = dec[b * H + tid];
        dsh[tid + 256] = dec[b * H + tid + 256];
        __syncthreads();
        float s0 = 0.f, s1 = 0.f;
#pragma unroll 8
        for (int d = 0; d < H; ++d) {
            float dv = dsh[d];
            s0 += dv * Wd[d * H + tid];
            s1 += dv * Wd[d * H + tid + 256];
        }
        g_proj_dec[b * H + tid]       = s0;
        g_proj_dec[b * H + tid + 256] = s1;
    }
}

// ---------------------------------------------------------------------------
// Kernel 2: scores via single-term fp16 mma.sync + fused tanh·v epilogue
// Block tile: 128(M) x 256(N), BK=32, 16 warps (2x8), warp tile 64x32.
// Grid: (2, 1024). blockIdx.x = n-pass (0/1), blockIdx.y = row block.
// ny=0 CTAs additionally write converted fp16 A rows to g_enc16 (byproduct,
// consumed by context_part; ~256MB STG absorbed by DRAM headroom).
// (R9 structure — do not reorder the loop; deviations cost 50-300us.)
// ---------------------------------------------------------------------------
#define KSTEPS 32   // 1024 / 32

// Dynamic SMEM layout (bytes)
#define SW_BUF   0         // 3 x 16384
#define SA_BUF   49152     // 2 x 8192
#define S_PD     65536     // 256 f32
#define S_V      66560     // 256 f32
#define S_RED    67584     // 128*8 f32 = 4KB
#define SM_TOT   71680

__global__ void __launch_bounds__(512, 1) scores_mma_kernel(
    const float* __restrict__ enc, const float* __restrict__ v)
{
    extern __shared__ char smem[];
    const uint32_t sb = smem_u32(smem);
    const int tid  = threadIdx.x;
    const int lane = tid & 31;
    const int warp = tid >> 5;
    const int wm   = warp >> 3;        // 0..1
    const int wn   = warp & 7;         // 0..7
    const int ny   = blockIdx.x;       // 0..1 (n-pass)
    const int row0 = blockIdx.y * 128;
    const int b    = row0 >> 11;       // S = 2048

    float* pd_sh = (float*)(smem + S_PD);
    float* v_sh  = (float*)(smem + S_V);
    float* red   = (float*)(smem + S_RED);
    if (tid < 256) {
        pd_sh[tid] = g_proj_dec[b * H + ny * 256 + tid];
        v_sh[tid]  = v[ny * 256 + tid];
    }

    // A (enc) load mapping: 4 threads per row, 8 k-elems (32B) each
    const int am = tid >> 2;           // 0..127
    const int ap = tid & 3;            // 16B group within 64B row
    const float* aptr = enc + (size_t)(row0 + am) * E + ap * 8;
    __half* e16ptr = g_enc16 + (size_t)(row0 + am) * E + ap * 8;

    const __half* wbase = g_Wh16 + ny * 256;

    float c[4][4][4];
#pragma unroll
    for (int mt = 0; mt < 4; mt++)
#pragma unroll
        for (int j = 0; j < 4; j++)
#pragma unroll
            for (int q = 0; q < 4; q++) c[mt][j][q] = 0.f;

    uint4 pref[2];

    // ---- lambdas ----
    auto issueW = [&](int st) {
        uint32_t wb = sb + SW_BUF + (uint32_t)(st % 3) * 16384u;
        const __half* bh = wbase + (size_t)(st * 32) * H;
#pragma unroll
        for (int it = 0; it < 2; it++) {
            int idx = tid + it * 512;
            int k = idx >> 5;          // 0..31
            int g = idx & 31;          // 16B group (8 fp16)
            uint32_t off = (uint32_t)(k * 512 + ((g ^ (k & 7)) << 4));
            cp16(wb + off, bh + (size_t)k * H + g * 8);
        }
    };
    auto ldA = [&](int st) {
        const float4* p = (const float4*)(aptr + st * 32);
        pref[0] = *(const uint4*)(p);
        pref[1] = *(const uint4*)(p + 1);
    };
    auto cvtStsA = [&](int st) {
        char* ab = smem + SA_BUF + (st & 1) * 8192;
        float4 f0 = *(float4*)&pref[0];
        float4 f1 = *(float4*)&pref[1];
        uint4 hv;
        hv.x = pack_h2(f0.x, f0.y);
        hv.y = pack_h2(f0.z, f0.w);
        hv.z = pack_h2(f1.x, f1.y);
        hv.w = pack_h2(f1.z, f1.w);
        uint32_t off = (uint32_t)(am * 64 + ((ap ^ ((am >> 1) & 3)) << 4));
        *(uint4*)(ab + off) = hv;
        if (ny == 0)
            *(uint4*)(e16ptr + st * 32) = hv;   // fp16 enc byproduct
    };
    auto doMMA = [&](int st) {
        uint32_t ab = sb + SA_BUF + (uint32_t)(st & 1) * 8192u;
        uint32_t wb = sb + SW_BUF + (uint32_t)(st % 3) * 16384u;
#pragma unroll
        for (int ks = 0; ks < 2; ks++) {
            uint32_t ah[4][4], bh[2][4];
            const int mrb = wm * 64 + (lane & 15);
            const int kg  = ks * 2 + (lane >> 4);
#pragma unroll
            for (int mt = 0; mt < 4; mt++) {
                int m = mrb + mt * 16;
                uint32_t off = (uint32_t)(m * 64 + ((kg ^ ((m >> 1) & 3)) << 4));
                ldsm_x4(ab + off, ah[mt]);
            }
            const int kr = ks * 16 + (lane & 7) + ((lane >> 3) & 1) * 8;
#pragma unroll
            for (int jj = 0; jj < 2; jj++) {
                int ng = wn * 4 + jj * 2 + (lane >> 4);
                uint32_t off = (uint32_t)(kr * 512 + ((ng ^ (kr & 7)) << 4));
                ldsm_x4_t(wb + off, bh[jj]);
            }
#pragma unroll
            for (int mt = 0; mt < 4; mt++)
#pragma unroll
                for (int j = 0; j < 4; j++) {
                    uint32_t b0 = bh[j >> 1][(j & 1) * 2];
                    uint32_t b1 = bh[j >> 1][(j & 1) * 2 + 1];
                    mma_fp16(c[mt][j], ah[mt], b0, b1);
                }
        }
    };

    // ---- prologue ----
    issueW(0); cp_commit();
    issueW(1); cp_commit();
    ldA(0);
    cvtStsA(0);
    cp_wait1();
    __syncthreads();

    // ---- main loop ----
    for (int i = 0; i < KSTEPS; i++) {
        const bool more = (i + 1 < KSTEPS);
        if (more) ldA(i + 1);
        if (i + 2 < KSTEPS) issueW(i + 2);
        cp_commit();                       // one group per iter (may be empty)
        doMMA(i);
        if (more) {
            cvtStsA(i + 1);
            cp_wait1();
            __syncthreads();
        }
    }

    // ---- epilogue: partial scores over this 256-n slice ----
    float p[4][2];
#pragma unroll
    for (int mt = 0; mt < 4; mt++) { p[mt][0] = 0.f; p[mt][1] = 0.f; }
#pragma unroll
    for (int mt = 0; mt < 4; mt++)
#pragma unroll
        for (int j = 0; j < 4; j++) {
            int nn = wn * 32 + j * 8 + ((lane & 3) << 1);
            float pd0 = pd_sh[nn], pd1 = pd_sh[nn + 1];
            float v0 = v_sh[nn], v1 = v_sh[nn + 1];
            p[mt][0] += tanh_hw(c[mt][j][0] + pd0) * v0 + tanh_hw(c[mt][j][1] + pd1) * v1;
            p[mt][1] += tanh_hw(c[mt][j][2] + pd0) * v0 + tanh_hw(c[mt][j][3] + pd1) * v1;
        }
#pragma unroll
    for (int mt = 0; mt < 4; mt++) {
        float p0 = p[mt][0], p1 = p[mt][1];
        p0 += __shfl_xor_sync(0xFFFFFFFF, p0, 1);
        p0 += __shfl_xor_sync(0xFFFFFFFF, p0, 2);
        p1 += __shfl_xor_sync(0xFFFFFFFF, p1, 1);
        p1 += __shfl_xor_sync(0xFFFFFFFF, p1, 2);
        if ((lane & 3) == 0) {
            int r = wm * 64 + mt * 16 + (lane >> 2);
            red[r * 8 + wn]       = p0;
            red[(r + 8) * 8 + wn] = p1;
        }
    }
    __syncthreads();
    if (tid < 128) {
        float s = 0.f;
#pragma unroll
        for (int t = 0; t < 8; t++) s += red[tid * 8 + t];
        g_scores_part[ny][row0 + tid] = s;
    }
}

// ---------------------------------------------------------------------------
// Kernel 3: mask + softmax. No max pass (scores bounded; masked -> exp = 0).
// ---------------------------------------------------------------------------
__global__ __launch_bounds__(512) void softmax_kernel(
    const int* __restrict__ mask, float* __restrict__ attn)
{
    __shared__ float buf[S];
    __shared__ float redv[512];
    const int b = blockIdx.x;
    const int tid = threadIdx.x;

    float sum = 0.f;
#pragma unroll
    for (int s = tid; s < S; s += 512) {
        float e = (mask[b * S + s] == 0)
                ? 0.0f
                : __expf(g_scores_part[0][b * S + s] + g_scores_part[1][b * S + s]);
        buf[s] = e;
        sum += e;
    }
    redv[tid] = sum;
    __syncthreads();
    for (int st = 256; st > 0; st >>= 1) {
        if (tid < st) redv[tid] += redv[tid + st];
        __syncthreads();
    }
    float inv = 1.0f / redv[0];
#pragma unroll
    for (int s = tid; s < S; s += 512)
        attn[b * S + s] = buf[s] * inv;
}

// ---------------------------------------------------------------------------
// Kernel 4: context partials from fp16 enc. grid (B, NCHUNK).
// Each thread owns 4 n-elements (uint2 = 4 halfs per s-row).
// ---------------------------------------------------------------------------
__global__ __launch_bounds__(256) void context_part_kernel(
    const float* __restrict__ attn)
{
    __shared__ float w[S / NCHUNK];
    const int b = blockIdx.x;
    const int chunk = blockIdx.y;
    const int tid = threadIdx.x;
    const int s0 = chunk * (S / NCHUNK);

    for (int s = tid; s < S / NCHUNK; s += 256)
        w[s] = attn[b * S + s0 + s];
    __syncthreads();

    const __half* erow = g_enc16 + ((size_t)b * S + s0) * E;
    float2 c0a = make_float2(0.f, 0.f), c0b = make_float2(0.f, 0.f);
    float2 c1a = make_float2(0.f, 0.f), c1b = make_float2(0.f, 0.f);
#pragma unroll 4
    for (int s = 0; s < S / NCHUNK; s += 2) {
        uint2 ua = *(const uint2*)(erow + (size_t)s * E + tid * 4);
        uint2 ub = *(const uint2*)(erow + (size_t)(s + 1) * E + tid * 4);
        float wa = w[s], wb = w[s + 1];
        float2 a0 = __half22float2(*(__half2*)&ua.x);
        float2 a1 = __half22float2(*(__half2*)&ua.y);
        float2 b0 = __half22float2(*(__half2*)&ub.x);
        float2 b1 = __half22float2(*(__half2*)&ub.y);
        c0a.x += wa * a0.x; c0a.y += wa * a0.y;
        c0b.x += wa * a1.x; c0b.y += wa * a1.y;
        c1a.x += wb * b0.x; c1a.y += wb * b0.y;
        c1b.x += wb * b1.x; c1b.y += wb * b1.y;
    }
    float4 c;
    c.x = c0a.x + c1a.x; c.y = c0a.y + c1a.y;
    c.z = c0b.x + c1b.x; c.w = c0b.y + c1b.y;
    ((float4*)(&g_ctx_part[chunk][b * E]))[tid] = c;
}

// ---------------------------------------------------------------------------
// Kernel 5: reduce context partials into d_out.
// ---------------------------------------------------------------------------
__global__ __launch_bounds__(256) void context_reduce_kernel(float* __restrict__ ctx)
{
    const int b = blockIdx.x;
    const int tid = threadIdx.x;
    float4 c = make_float4(0.f, 0.f, 0.f, 0.f);
#pragma unroll
    for (int ch = 0; ch < NCHUNK; ++ch) {
        float4 p = ((const float4*)(&g_ctx_part[ch][b * E]))[tid];
        c.x += p.x; c.y += p.y; c.z += p.z; c.w += p.w;
    }
    ((float4*)(ctx + b * E))[tid] = c;
}

// ---------------------------------------------------------------------------
extern "C" void kernel_launch(void* const* d_in, const int* in_sizes, int n_in,
                              void* d_out, int out_size)
{
    const float* dec  = (const float*)d_in[0];  // (B, H)
    const float* enc  = (const float*)d_in[1];  // (B, S, 2H)
    const int*   mask = (const int*)  d_in[2];  // (B, S)
    const float* Wh   = (const float*)d_in[3];  // (2H, H)
    const float* Wd   = (const float*)d_in[4];  // (H, H)
    const float* v    = (const float*)d_in[5];  // (H,)

    float* out  = (float*)d_out;
    float* ctx  = out;             // (B, 2H)
    float* attn = out + B * E;     // (B, S)

    cudaFuncSetAttribute(scores_mma_kernel,
                         cudaFuncAttributeMaxDynamicSharedMemorySize, SM_TOT);

    prep_kernel<<<(E * H) / 256 + B, 256>>>(Wh, dec, Wd);
    dim3 gs(2, (B * S) / 128);
    scores_mma_kernel<<<gs, 512, SM_TOT>>>(enc, v);
    softmax_kernel<<<B, 512>>>(mask, attn);
    dim3 gctx(B, NCHUNK);
    context_part_kernel<<<gctx, 256>>>(attn);
    context_reduce_kernel<<<B, 256>>>(ctx);
}